// round 12
// baseline (speedup 1.0000x reference)
#include <cuda_runtime.h>
#include <cuda_fp16.h>

// Problem constants
static constexpr int LD  = 4;       // LOCAL_DIM
static constexpr int MD  = 64;      // M
static constexpr int TRI = 89440;   // sum_{k=1..64} k^2

// epsilon strides (elements): shape (4, 64, 64, 65, 65) = (d, m, l, u, dn)
static constexpr unsigned long long SD = 17305600ull; // 64*64*65*65
static constexpr unsigned long long SM = 270400ull;   // 64*65*65
static constexpr unsigned long long SL = 4225ull;     // 65*65

// Scratch: fp16 LOG of the covered region, layout [d][loff(l)+u*(l+1)+dn][m/2]
__device__ __half2 g_scratch2[(size_t)LD * TRI * (MD / 2)];

// Realized ranges per (d,l): 0 = max u, 1 = max(63-u), 2 = max dn, 3 = max(63-dn).
__device__ int g_rng[4][LD][64];

__device__ __host__ __forceinline__ int loff(int l) {
    return l * (l + 1) * (2 * l + 1) / 6;
}

// Static +-4.5 sigma band for Binomial(l, 1/2): halfwidth 2.25*sqrt(l).
__device__ __forceinline__ void static_band(int l, int& lo, int& hi) {
    const float h = 2.25f * sqrtf((float)l);
    lo = max(0, (int)floorf(0.5f * (float)l - h));
    hi = min(l, (int)ceilf(0.5f * (float)l + h));
}

// Per-warp dtype detection (int64 vs int32 indices; values < 4).
__device__ __forceinline__ bool detect_is64(const void* raw, int lane) {
    unsigned wodd = ((const unsigned*)raw)[2 * lane + 1];
    return __ballot_sync(0xffffffffu, wodd != 0u) == 0u;
}

__device__ __forceinline__ int load_idx(const void* raw, size_t pos, bool is64) {
    if (is64) return (int)((const long long*)raw)[pos];
    return ((const int*)raw)[pos];
}

// Shared transpose worker: copy eps[d,:,l,u,dn0..dn1] -> log-fp16 scratch rows.
// Uniform (dn0,dn1) per block; all threads participate. tile reusable after.
__device__ __forceinline__ void transpose_rows(const float* __restrict__ eps,
                                               float (*tile)[65],
                                               int d, int l, int u, int dn0, int dn1) {
    if (dn0 > dn1) return;
    const int W  = dn1 - dn0;
    const int tx = threadIdx.x;      // 0..31
    const int ty = threadIdx.y;      // 0..7

    const size_t in0 = (size_t)d * SD + (size_t)l * SL + (size_t)u * 65ull + dn0;
    #pragma unroll
    for (int m = ty; m < 64; m += 8) {
        const size_t r = in0 + (size_t)m * SM;
        if (tx <= W)      tile[m][tx]      = __logf(eps[r + tx]);
        if (tx + 32 <= W) tile[m][tx + 32] = __logf(eps[r + tx + 32]);
    }
    __syncthreads();

    const size_t ob2 = ((size_t)d * TRI + (size_t)loff(l) + (size_t)u * (l + 1)) * 32ull;
    for (int dn = dn0 + ty; dn <= dn1; dn += 8) {
        const int c = dn - dn0;
        g_scratch2[ob2 + (size_t)dn * 32ull + tx] =
            __floats2half2_rn(tile[2 * tx][c], tile[2 * tx + 1][c]);
    }
    __syncthreads();
}

// ---------------------------------------------------------------------------
// Kernel 1 (fused): z==0 -> mark blocks (lowest block ids: scheduled first),
// z in 1..4 -> static-band transpose for d = z-1. Mark (2 MB reads, latency-
// bound) overlaps the DRAM-bound transpose for free.
// block (32,8); grid (64, 64, 5).
// ---------------------------------------------------------------------------
__global__ void __launch_bounds__(256) fused_mark_transpose(const float* __restrict__ eps,
                                                            const void* __restrict__ raw) {
    __shared__ float tile[64][65];
    __shared__ int   s_rng[4][LD][64];

    const int z = blockIdx.z;
    if (z == 0) {
        // ---- mark ranges: 256 active blocks (y<4), 32 batches each ----
        if (blockIdx.y >= 4) return;
        const int group = blockIdx.y * 64 + blockIdx.x;   // 0..255
        const int t     = threadIdx.y * 32 + threadIdx.x; // 0..255
        const int w     = t >> 5;
        const int lane  = t & 31;

        for (int i = t; i < 4 * LD * 64; i += 256)
            (&s_rng[0][0][0])[i] = 0;
        const bool is64 = detect_is64(raw, lane);
        __syncthreads();

        int i0[4], i1[4];
        #pragma unroll
        for (int p = 0; p < 4; ++p) {
            const size_t base = ((size_t)(group * 32 + w * 4 + p)) * 64;
            i0[p] = load_idx(raw, base + lane,      is64);
            i1[p] = load_idx(raw, base + lane + 32, is64);
        }

        const unsigned lm = (1u << lane) - 1u;
        #pragma unroll
        for (int p = 0; p < 4; ++p) {
            const unsigned m0lo = __ballot_sync(0xffffffffu, i0[p] & 1);
            const unsigned m1lo = __ballot_sync(0xffffffffu, i0[p] & 2);
            const unsigned m0hi = __ballot_sync(0xffffffffu, i1[p] & 1);
            const unsigned m1hi = __ballot_sync(0xffffffffu, i1[p] & 2);

            const int u_lo  = __popc(m0lo & lm);
            const int dn_lo = __popc(m1lo & lm);
            const int u_hi  = __popc(m0lo) + __popc(m0hi & lm);
            const int dn_hi = __popc(m1lo) + __popc(m1hi & lm);

            atomicMax(&s_rng[0][i0[p]][lane],      u_lo);
            atomicMax(&s_rng[1][i0[p]][lane],      63 - u_lo);
            atomicMax(&s_rng[2][i0[p]][lane],      dn_lo);
            atomicMax(&s_rng[3][i0[p]][lane],      63 - dn_lo);
            atomicMax(&s_rng[0][i1[p]][lane + 32], u_hi);
            atomicMax(&s_rng[1][i1[p]][lane + 32], 63 - u_hi);
            atomicMax(&s_rng[2][i1[p]][lane + 32], dn_hi);
            atomicMax(&s_rng[3][i1[p]][lane + 32], 63 - dn_hi);
        }
        __syncthreads();

        #pragma unroll
        for (int k = 0; k < 4; ++k) {
            const int i = t + 256 * k;
            const int v = (&s_rng[0][0][0])[i];
            if (v > 0) atomicMax(&(&g_rng[0][0][0])[i], v);
        }
        return;
    }

    // ---- static-band transpose ----
    const int d = z - 1;
    const int l = blockIdx.x;
    const int u = blockIdx.y;
    if (u > l) return;

    int ulo, uhi, nlo, nhi;
    static_band(l, ulo, uhi);
    if (u < ulo || u > uhi) return;
    static_band(l, nlo, nhi);   // same band for dn
    transpose_rows(eps, tile, d, l, u, nlo, nhi);
}

// ---------------------------------------------------------------------------
// Kernel 2 (shell): cover realized rectangle minus the static band.
// block (32,8); grid (64, 64, 4). Almost all blocks exit after 4 loads.
// ---------------------------------------------------------------------------
__global__ void __launch_bounds__(256) eps_shell(const float* __restrict__ eps) {
    const int l = blockIdx.x;
    const int u = blockIdx.y;
    const int d = blockIdx.z;
    if (u > l) return;

    const int umax = g_rng[0][d][l];
    const int umin = 63 - g_rng[1][d][l];
    if (u < umin || u > umax) return;
    const int dmax = g_rng[2][d][l];
    const int dmin = 63 - g_rng[3][d][l];
    if (dmin > dmax) return;

    int ulo, uhi, nlo, nhi;
    static_band(l, ulo, uhi);
    static_band(l, nlo, nhi);

    __shared__ float tile[64][65];

    if (u < ulo || u > uhi) {
        // Row not covered by kernel 1 at all: copy the full realized dn range.
        transpose_rows(eps, tile, d, l, u, dmin, dmax);
    } else {
        // Covered [nlo..nhi] already; add the two outer segments if realized.
        transpose_rows(eps, tile, d, l, u, dmin, min(dmax, nlo - 1));
        transpose_rows(eps, tile, d, l, u, max(dmin, nhi + 1), dmax);
    }
}

// ---------------------------------------------------------------------------
// Kernel 3: warp-per-batch compute (unchanged from R11).
// ---------------------------------------------------------------------------
__global__ void __launch_bounds__(256) seggps_compute(const void* __restrict__ raw,
                                                      float* __restrict__ out) {
    __shared__ unsigned s_base[8][64];

    const int t    = threadIdx.x;
    const int w    = t >> 5;
    const int lane = t & 31;
    const int b    = blockIdx.x * 8 + w;

    const bool is64 = detect_is64(raw, lane);
    const size_t base = (size_t)b * 64;
    const int i0 = load_idx(raw, base + lane,      is64);
    const int i1 = load_idx(raw, base + lane + 32, is64);

    const unsigned m0lo = __ballot_sync(0xffffffffu, i0 & 1);
    const unsigned m1lo = __ballot_sync(0xffffffffu, i0 & 2);
    const unsigned m0hi = __ballot_sync(0xffffffffu, i1 & 1);
    const unsigned m1hi = __ballot_sync(0xffffffffu, i1 & 2);

    const unsigned lm = (1u << lane) - 1u;
    const int u_lo  = __popc(m0lo & lm);
    const int dn_lo = __popc(m1lo & lm);
    const int u_hi  = __popc(m0lo) + __popc(m0hi & lm);
    const int dn_hi = __popc(m1lo) + __popc(m1hi & lm);

    const int s_hi = lane + 32;
    s_base[w][lane] = (unsigned)((i0 * TRI + loff(lane) + u_lo * (lane + 1) + dn_lo) * 32);
    s_base[w][s_hi] = (unsigned)((i1 * TRI + loff(s_hi) + u_hi * (s_hi + 1) + dn_hi) * 32);
    __syncwarp();

    float2 a0 = {0.f, 0.f}, a1 = {0.f, 0.f}, a2 = {0.f, 0.f}, a3 = {0.f, 0.f};
    float2 a4 = {0.f, 0.f}, a5 = {0.f, 0.f}, a6 = {0.f, 0.f}, a7 = {0.f, 0.f};
    #pragma unroll
    for (int l = 0; l < 64; l += 8) {
        const float2 v0 = __half22float2(g_scratch2[s_base[w][l + 0] + lane]);
        const float2 v1 = __half22float2(g_scratch2[s_base[w][l + 1] + lane]);
        const float2 v2 = __half22float2(g_scratch2[s_base[w][l + 2] + lane]);
        const float2 v3 = __half22float2(g_scratch2[s_base[w][l + 3] + lane]);
        const float2 v4 = __half22float2(g_scratch2[s_base[w][l + 4] + lane]);
        const float2 v5 = __half22float2(g_scratch2[s_base[w][l + 5] + lane]);
        const float2 v6 = __half22float2(g_scratch2[s_base[w][l + 6] + lane]);
        const float2 v7 = __half22float2(g_scratch2[s_base[w][l + 7] + lane]);
        a0.x += v0.x; a0.y += v0.y;  a1.x += v1.x; a1.y += v1.y;
        a2.x += v2.x; a2.y += v2.y;  a3.x += v3.x; a3.y += v3.y;
        a4.x += v4.x; a4.y += v4.y;  a5.x += v5.x; a5.y += v5.y;
        a6.x += v6.x; a6.y += v6.y;  a7.x += v7.x; a7.y += v7.y;
    }
    const float sx = ((a0.x + a1.x) + (a2.x + a3.x)) + ((a4.x + a5.x) + (a6.x + a7.x));
    const float sy = ((a0.y + a1.y) + (a2.y + a3.y)) + ((a4.y + a5.y) + (a6.y + a7.y));

    float p = __expf(sx) + __expf(sy);
    #pragma unroll
    for (int o = 16; o > 0; o >>= 1)
        p += __shfl_xor_sync(0xffffffffu, p, o);
    if (lane == 0) out[b] = p;
}

// ---------------------------------------------------------------------------
extern "C" void kernel_launch(void* const* d_in, const int* in_sizes, int n_in,
                              void* d_out, int out_size) {
    const float* eps = (const float*)d_in[1];
    float*       out = (float*)d_out;

    fused_mark_transpose<<<dim3(64, 64, 5), dim3(32, 8)>>>(eps, d_in[0]);
    eps_shell           <<<dim3(64, 64, 4), dim3(32, 8)>>>(eps);
    seggps_compute      <<<8192 / 8, 256>>>(d_in[0], out);
}

// round 14
// speedup vs baseline: 1.6567x; 1.6567x over previous
#include <cuda_runtime.h>
#include <cuda_fp16.h>

// Problem constants
static constexpr int LD  = 4;       // LOCAL_DIM
static constexpr int MD  = 64;      // M
static constexpr int TRI = 89440;   // sum_{k=1..64} k^2

// epsilon strides (elements): shape (4, 64, 64, 65, 65) = (d, m, l, u, dn)
static constexpr unsigned long long SD = 17305600ull; // 64*64*65*65
static constexpr unsigned long long SM = 270400ull;   // 64*65*65
static constexpr unsigned long long SL = 4225ull;     // 65*65

static constexpr int NGROUP = 256;  // batch groups for the range pass

// Scratch: fp16 LOG2 of the realized region, layout [d][loff(l)+u*(l+1)+dn][m/2]
__device__ __half2 g_scratch2[(size_t)LD * TRI * (MD / 2)];

// Realized ranges per (d,l): 0 = max u, 1 = max(63-u), 2 = max dn, 3 = max(63-dn).
// Zero-init at load; atomicMax converges to the same fixed point each replay.
__device__ int g_rng[4][LD][64];

__device__ __host__ __forceinline__ int loff(int l) {
    return l * (l + 1) * (2 * l + 1) / 6;
}

// Per-warp dtype detection (int64 vs int32 indices; values < 4).
__device__ __forceinline__ bool detect_is64(const void* raw, int lane) {
    unsigned wodd = ((const unsigned*)raw)[2 * lane + 1];
    return __ballot_sync(0xffffffffu, wodd != 0u) == 0u;
}

__device__ __forceinline__ int load_idx(const void* raw, size_t pos, bool is64) {
    if (is64) return (int)((const long long*)raw)[pos];
    return ((const int*)raw)[pos];
}

// ---------------------------------------------------------------------------
// Kernel 1: realized (u,dn) range per (d,l). Grid 256 x 256 thr; warp w
// handles 4 batches; lane owns sites (lane, lane+32). Intra-warp ballots only;
// smem atomicMax aggregation; 1024 spread global REDs per block at the end.
// (R10 config: measured 7.0 us.)
// ---------------------------------------------------------------------------
__global__ void __launch_bounds__(256) mark_ranges(const void* __restrict__ raw) {
    const int t     = threadIdx.x;
    const int w     = t >> 5;
    const int lane  = t & 31;
    const int group = blockIdx.x;          // 0..255

    __shared__ int s_rng[4][LD][64];       // 4 KB
    for (int i = t; i < 4 * LD * 64; i += 256)
        (&s_rng[0][0][0])[i] = 0;
    const bool is64 = detect_is64(raw, lane);
    __syncthreads();

    int i0[4], i1[4];
    #pragma unroll
    for (int p = 0; p < 4; ++p) {
        const size_t base = ((size_t)(group * 32 + w * 4 + p)) * 64;
        i0[p] = load_idx(raw, base + lane,      is64);
        i1[p] = load_idx(raw, base + lane + 32, is64);
    }

    const unsigned lm = (1u << lane) - 1u;
    #pragma unroll
    for (int p = 0; p < 4; ++p) {
        const unsigned m0lo = __ballot_sync(0xffffffffu, i0[p] & 1);
        const unsigned m1lo = __ballot_sync(0xffffffffu, i0[p] & 2);
        const unsigned m0hi = __ballot_sync(0xffffffffu, i1[p] & 1);
        const unsigned m1hi = __ballot_sync(0xffffffffu, i1[p] & 2);

        const int u_lo  = __popc(m0lo & lm);
        const int dn_lo = __popc(m1lo & lm);
        const int u_hi  = __popc(m0lo) + __popc(m0hi & lm);
        const int dn_hi = __popc(m1lo) + __popc(m1hi & lm);

        atomicMax(&s_rng[0][i0[p]][lane],      u_lo);
        atomicMax(&s_rng[1][i0[p]][lane],      63 - u_lo);
        atomicMax(&s_rng[2][i0[p]][lane],      dn_lo);
        atomicMax(&s_rng[3][i0[p]][lane],      63 - dn_lo);
        atomicMax(&s_rng[0][i1[p]][lane + 32], u_hi);
        atomicMax(&s_rng[1][i1[p]][lane + 32], 63 - u_hi);
        atomicMax(&s_rng[2][i1[p]][lane + 32], dn_hi);
        atomicMax(&s_rng[3][i1[p]][lane + 32], 63 - dn_hi);
    }
    __syncthreads();

    #pragma unroll
    for (int k = 0; k < 4; ++k) {
        const int i = t + 256 * k;
        const int v = (&s_rng[0][0][0])[i];
        if (v > 0) atomicMax(&(&g_rng[0][0][0])[i], v);
    }
}

// ---------------------------------------------------------------------------
// Kernel 2: transpose eps[d, m, l, u, dn] -> log2-fp16 scratch[d, tri, m/2],
// only the realized rectangle per (d,l). Uniform-width fast path: when the
// dn band fits in 32 columns (~80% of blocks) the whole second load column
// is skipped -> near-halves issued instructions of this issue-bound kernel.
// block (32,8); grid (l=64, u=64, d=4).
// ---------------------------------------------------------------------------
__global__ void __launch_bounds__(256) eps_transpose(const float* __restrict__ eps) {
    const int l = blockIdx.x;
    const int u = blockIdx.y;
    const int d = blockIdx.z;

    const int umax  = g_rng[0][d][l];
    const int umin  = 63 - g_rng[1][d][l];
    if (u < umin || u > umax) return;
    const int dn1   = g_rng[2][d][l];          // dnmax
    const int dn0   = 63 - g_rng[3][d][l];     // dnmin
    if (dn0 > dn1) return;
    const int W = dn1 - dn0;                   // band width - 1 (uniform)

    const int tx = threadIdx.x;      // 0..31
    const int ty = threadIdx.y;      // 0..7

    __shared__ float tile[64][65];   // [m][dn-dn0], log2 values, padded

    const size_t in0 = (size_t)d * SD + (size_t)l * SL + (size_t)u * 65ull + dn0;
    if (W < 32) {
        // Fast path: single 32-lane column covers the band.
        #pragma unroll
        for (int m = ty; m < 64; m += 8) {
            const size_t r = in0 + (size_t)m * SM;
            if (tx <= W) tile[m][tx] = __log2f(eps[r + tx]);
        }
    } else {
        #pragma unroll
        for (int m = ty; m < 64; m += 8) {
            const size_t r = in0 + (size_t)m * SM;
            tile[m][tx] = __log2f(eps[r + tx]);
            if (tx + 32 <= W) tile[m][tx + 32] = __log2f(eps[r + tx + 32]);
        }
    }
    __syncthreads();

    // Row of 32 half2 (m-pairs) per realized dn; coalesced 128B stores.
    const size_t ob2 = ((size_t)d * TRI + (size_t)loff(l) + (size_t)u * (l + 1)) * 32ull;
    for (int dn = dn0 + ty; dn <= dn1; dn += 8) {
        const int c = dn - dn0;
        g_scratch2[ob2 + (size_t)dn * 32ull + tx] =
            __floats2half2_rn(tile[2 * tx][c], tile[2 * tx + 1][c]);
    }
}

// ---------------------------------------------------------------------------
// Kernel 3: warp-per-batch compute. Lane owns sites (lane, lane+32) for the
// scan and m-pair (2*lane, 2*lane+1) for accumulation. No block barriers.
// Sum fp32 log2s over 64 sites (8x float2 accumulators), exp2, reduce over m.
// ---------------------------------------------------------------------------
__global__ void __launch_bounds__(256) seggps_compute(const void* __restrict__ raw,
                                                      float* __restrict__ out) {
    __shared__ unsigned s_base[8][64];

    const int t    = threadIdx.x;
    const int w    = t >> 5;
    const int lane = t & 31;
    const int b    = blockIdx.x * 8 + w;

    const bool is64 = detect_is64(raw, lane);
    const size_t base = (size_t)b * 64;
    const int i0 = load_idx(raw, base + lane,      is64);
    const int i1 = load_idx(raw, base + lane + 32, is64);

    const unsigned m0lo = __ballot_sync(0xffffffffu, i0 & 1);
    const unsigned m1lo = __ballot_sync(0xffffffffu, i0 & 2);
    const unsigned m0hi = __ballot_sync(0xffffffffu, i1 & 1);
    const unsigned m1hi = __ballot_sync(0xffffffffu, i1 & 2);

    const unsigned lm = (1u << lane) - 1u;
    const int u_lo  = __popc(m0lo & lm);
    const int dn_lo = __popc(m1lo & lm);
    const int u_hi  = __popc(m0lo) + __popc(m0hi & lm);
    const int dn_hi = __popc(m1lo) + __popc(m1hi & lm);

    const int s_hi = lane + 32;
    s_base[w][lane] = (unsigned)((i0 * TRI + loff(lane) + u_lo * (lane + 1) + dn_lo) * 32);
    s_base[w][s_hi] = (unsigned)((i1 * TRI + loff(s_hi) + u_hi * (s_hi + 1) + dn_hi) * 32);
    __syncwarp();

    float2 a0 = {0.f, 0.f}, a1 = {0.f, 0.f}, a2 = {0.f, 0.f}, a3 = {0.f, 0.f};
    float2 a4 = {0.f, 0.f}, a5 = {0.f, 0.f}, a6 = {0.f, 0.f}, a7 = {0.f, 0.f};
    #pragma unroll
    for (int l = 0; l < 64; l += 8) {
        const float2 v0 = __half22float2(g_scratch2[s_base[w][l + 0] + lane]);
        const float2 v1 = __half22float2(g_scratch2[s_base[w][l + 1] + lane]);
        const float2 v2 = __half22float2(g_scratch2[s_base[w][l + 2] + lane]);
        const float2 v3 = __half22float2(g_scratch2[s_base[w][l + 3] + lane]);
        const float2 v4 = __half22float2(g_scratch2[s_base[w][l + 4] + lane]);
        const float2 v5 = __half22float2(g_scratch2[s_base[w][l + 5] + lane]);
        const float2 v6 = __half22float2(g_scratch2[s_base[w][l + 6] + lane]);
        const float2 v7 = __half22float2(g_scratch2[s_base[w][l + 7] + lane]);
        a0.x += v0.x; a0.y += v0.y;  a1.x += v1.x; a1.y += v1.y;
        a2.x += v2.x; a2.y += v2.y;  a3.x += v3.x; a3.y += v3.y;
        a4.x += v4.x; a4.y += v4.y;  a5.x += v5.x; a5.y += v5.y;
        a6.x += v6.x; a6.y += v6.y;  a7.x += v7.x; a7.y += v7.y;
    }
    const float sx = ((a0.x + a1.x) + (a2.x + a3.x)) + ((a4.x + a5.x) + (a6.x + a7.x));
    const float sy = ((a0.y + a1.y) + (a2.y + a3.y)) + ((a4.y + a5.y) + (a6.y + a7.y));

    float p = exp2f(sx) + exp2f(sy);
    #pragma unroll
    for (int o = 16; o > 0; o >>= 1)
        p += __shfl_xor_sync(0xffffffffu, p, o);
    if (lane == 0) out[b] = p;
}

// ---------------------------------------------------------------------------
extern "C" void kernel_launch(void* const* d_in, const int* in_sizes, int n_in,
                              void* d_out, int out_size) {
    const float* eps = (const float*)d_in[1];
    float*       out = (float*)d_out;

    mark_ranges  <<<NGROUP, 256>>>(d_in[0]);
    eps_transpose<<<dim3(64, 64, 4), dim3(32, 8)>>>(eps);
    seggps_compute<<<8192 / 8, 256>>>(d_in[0], out);
}

// round 16
// speedup vs baseline: 1.8481x; 1.1156x over previous
#include <cuda_runtime.h>
#include <cuda_fp16.h>

// Problem constants
static constexpr int LD  = 4;       // LOCAL_DIM
static constexpr int MD  = 64;      // M
static constexpr int TRI = 89440;   // sum_{k=1..64} k^2

// epsilon strides (elements): shape (4, 64, 64, 65, 65) = (d, m, l, u, dn)
static constexpr unsigned long long SD = 17305600ull; // 64*64*65*65
static constexpr unsigned long long SM = 270400ull;   // 64*65*65
static constexpr unsigned long long SL = 4225ull;     // 65*65

static constexpr int NGROUP = 256;  // batch groups for the range pass

// Scratch: fp16 LOG2 of the realized region, layout [d][loff(l)+u*(l+1)+dn][m/2]
__device__ __half2 g_scratch2[(size_t)LD * TRI * (MD / 2)];

// Per-group range partials (plain stores; no global atomics) and final ranges.
// Entry layout (1024 ints): [metric 0..3][d 0..3][l 0..63];
// metric 0 = max u, 1 = max(63-u), 2 = max dn, 3 = max(63-dn).
__device__ int g_part[NGROUP][1024];
__device__ int g_rng[4][LD][64];

__device__ __host__ __forceinline__ int loff(int l) {
    return l * (l + 1) * (2 * l + 1) / 6;
}

// Per-warp dtype detection (int64 vs int32 indices; values < 4).
__device__ __forceinline__ bool detect_is64(const void* raw, int lane) {
    unsigned wodd = ((const unsigned*)raw)[2 * lane + 1];
    return __ballot_sync(0xffffffffu, wodd != 0u) == 0u;
}

__device__ __forceinline__ int load_idx(const void* raw, size_t pos, bool is64) {
    if (is64) return (int)((const long long*)raw)[pos];
    return ((const int*)raw)[pos];
}

// ---------------------------------------------------------------------------
// Kernel 1: per-group (u,dn) range partials. Grid 256 x 256 thr; warp w
// handles 4 batches; lane owns sites (lane, lane+32). Intra-warp ballots,
// smem atomicMax aggregation, then PLAIN coalesced stores of the partial.
// ---------------------------------------------------------------------------
__global__ void __launch_bounds__(256) mark_partial(const void* __restrict__ raw) {
    const int t     = threadIdx.x;
    const int w     = t >> 5;
    const int lane  = t & 31;
    const int group = blockIdx.x;          // 0..255

    __shared__ int s_rng[4][LD][64];       // 4 KB
    for (int i = t; i < 1024; i += 256)
        (&s_rng[0][0][0])[i] = 0;
    const bool is64 = detect_is64(raw, lane);
    __syncthreads();

    int i0[4], i1[4];
    #pragma unroll
    for (int p = 0; p < 4; ++p) {
        const size_t base = ((size_t)(group * 32 + w * 4 + p)) * 64;
        i0[p] = load_idx(raw, base + lane,      is64);
        i1[p] = load_idx(raw, base + lane + 32, is64);
    }

    const unsigned lm = (1u << lane) - 1u;
    #pragma unroll
    for (int p = 0; p < 4; ++p) {
        const unsigned m0lo = __ballot_sync(0xffffffffu, i0[p] & 1);
        const unsigned m1lo = __ballot_sync(0xffffffffu, i0[p] & 2);
        const unsigned m0hi = __ballot_sync(0xffffffffu, i1[p] & 1);
        const unsigned m1hi = __ballot_sync(0xffffffffu, i1[p] & 2);

        const int u_lo  = __popc(m0lo & lm);
        const int dn_lo = __popc(m1lo & lm);
        const int u_hi  = __popc(m0lo) + __popc(m0hi & lm);
        const int dn_hi = __popc(m1lo) + __popc(m1hi & lm);

        atomicMax(&s_rng[0][i0[p]][lane],      u_lo);
        atomicMax(&s_rng[1][i0[p]][lane],      63 - u_lo);
        atomicMax(&s_rng[2][i0[p]][lane],      dn_lo);
        atomicMax(&s_rng[3][i0[p]][lane],      63 - dn_lo);
        atomicMax(&s_rng[0][i1[p]][lane + 32], u_hi);
        atomicMax(&s_rng[1][i1[p]][lane + 32], 63 - u_hi);
        atomicMax(&s_rng[2][i1[p]][lane + 32], dn_hi);
        atomicMax(&s_rng[3][i1[p]][lane + 32], 63 - dn_hi);
    }
    __syncthreads();

    #pragma unroll
    for (int k = 0; k < 4; ++k) {
        const int i = t + 256 * k;
        g_part[group][i] = (&s_rng[0][0][0])[i];
    }
}

// ---------------------------------------------------------------------------
// Kernel 1b: reduce 256 partials -> g_rng. Grid 64 x 256 thr. Each thread
// max-folds 16 partials for one entry (MLP 16); smem tree finishes.
// ---------------------------------------------------------------------------
__global__ void __launch_bounds__(256) reduce_rng() {
    const int t       = threadIdx.x;
    const int e_local = t & 15;                     // entry within block
    const int grp     = t >> 4;                     // partial chunk 0..15
    const int entry   = blockIdx.x * 16 + e_local;  // 0..1023

    int v = 0;
    #pragma unroll
    for (int k = 0; k < 16; ++k)
        v = max(v, g_part[grp * 16 + k][entry]);

    __shared__ int s[16][17];
    s[e_local][grp] = v;
    __syncthreads();
    if (t < 16) {
        int m = 0;
        #pragma unroll
        for (int g = 0; g < 16; ++g) m = max(m, s[t][g]);
        (&g_rng[0][0][0])[blockIdx.x * 16 + t] = m;
    }
}

// ---------------------------------------------------------------------------
// Kernel 2: transpose eps -> log2-fp16 scratch, realized rectangle only.
// Each block handles a u-PAIR (u0 = 2*by, u0+1): 16 front-batched loads per
// thread (MLP 16), half the blocks. block (32,8); grid (64, 32, 4).
// ---------------------------------------------------------------------------
__global__ void __launch_bounds__(256) eps_transpose(const float* __restrict__ eps) {
    const int l  = blockIdx.x;
    const int u0 = 2 * blockIdx.y;
    const int u1 = u0 + 1;
    const int d  = blockIdx.z;

    const int umax = g_rng[0][d][l];
    const int umin = 63 - g_rng[1][d][l];
    const bool v0 = (u0 >= umin) && (u0 <= umax);
    const bool v1 = (u1 >= umin) && (u1 <= umax);
    if (!v0 && !v1) return;
    const int dn1 = g_rng[2][d][l];          // dnmax
    const int dn0 = 63 - g_rng[3][d][l];     // dnmin
    if (dn0 > dn1) return;
    const int W = dn1 - dn0;                 // band width - 1 (uniform per (d,l))

    const int tx = threadIdx.x;      // 0..31
    const int ty = threadIdx.y;      // 0..7

    __shared__ float tile[2][64][65];   // [u-parity][m][dn-dn0], padded

    const size_t inA = (size_t)d * SD + (size_t)l * SL + (size_t)u0 * 65ull + dn0;
    const size_t inB = inA + 65ull;
    if (W < 32) {
        #pragma unroll
        for (int m = ty; m < 64; m += 8) {
            const size_t rA = inA + (size_t)m * SM;
            const size_t rB = inB + (size_t)m * SM;
            if (v0 && tx <= W) tile[0][m][tx] = __log2f(eps[rA + tx]);
            if (v1 && tx <= W) tile[1][m][tx] = __log2f(eps[rB + tx]);
        }
    } else {
        #pragma unroll
        for (int m = ty; m < 64; m += 8) {
            const size_t rA = inA + (size_t)m * SM;
            const size_t rB = inB + (size_t)m * SM;
            if (v0) {
                tile[0][m][tx] = __log2f(eps[rA + tx]);
                if (tx + 32 <= W) tile[0][m][tx + 32] = __log2f(eps[rA + tx + 32]);
            }
            if (v1) {
                tile[1][m][tx] = __log2f(eps[rB + tx]);
                if (tx + 32 <= W) tile[1][m][tx + 32] = __log2f(eps[rB + tx + 32]);
            }
        }
    }
    __syncthreads();

    const size_t obA = ((size_t)d * TRI + (size_t)loff(l) + (size_t)u0 * (l + 1)) * 32ull;
    const size_t obB = obA + (size_t)(l + 1) * 32ull;
    for (int dn = dn0 + ty; dn <= dn1; dn += 8) {
        const int c = dn - dn0;
        if (v0) g_scratch2[obA + (size_t)dn * 32ull + tx] =
            __floats2half2_rn(tile[0][2 * tx][c], tile[0][2 * tx + 1][c]);
        if (v1) g_scratch2[obB + (size_t)dn * 32ull + tx] =
            __floats2half2_rn(tile[1][2 * tx][c], tile[1][2 * tx + 1][c]);
    }
}

// ---------------------------------------------------------------------------
// Kernel 3: warp-per-batch compute. Lane owns sites (lane, lane+32) for the
// scan and m-pair (2*lane, 2*lane+1) for accumulation. No block barriers.
// ---------------------------------------------------------------------------
__global__ void __launch_bounds__(256) seggps_compute(const void* __restrict__ raw,
                                                      float* __restrict__ out) {
    __shared__ unsigned s_base[8][64];

    const int t    = threadIdx.x;
    const int w    = t >> 5;
    const int lane = t & 31;
    const int b    = blockIdx.x * 8 + w;

    const bool is64 = detect_is64(raw, lane);
    const size_t base = (size_t)b * 64;
    const int i0 = load_idx(raw, base + lane,      is64);
    const int i1 = load_idx(raw, base + lane + 32, is64);

    const unsigned m0lo = __ballot_sync(0xffffffffu, i0 & 1);
    const unsigned m1lo = __ballot_sync(0xffffffffu, i0 & 2);
    const unsigned m0hi = __ballot_sync(0xffffffffu, i1 & 1);
    const unsigned m1hi = __ballot_sync(0xffffffffu, i1 & 2);

    const unsigned lm = (1u << lane) - 1u;
    const int u_lo  = __popc(m0lo & lm);
    const int dn_lo = __popc(m1lo & lm);
    const int u_hi  = __popc(m0lo) + __popc(m0hi & lm);
    const int dn_hi = __popc(m1lo) + __popc(m1hi & lm);

    const int s_hi = lane + 32;
    s_base[w][lane] = (unsigned)((i0 * TRI + loff(lane) + u_lo * (lane + 1) + dn_lo) * 32);
    s_base[w][s_hi] = (unsigned)((i1 * TRI + loff(s_hi) + u_hi * (s_hi + 1) + dn_hi) * 32);
    __syncwarp();

    float2 a0 = {0.f, 0.f}, a1 = {0.f, 0.f}, a2 = {0.f, 0.f}, a3 = {0.f, 0.f};
    float2 a4 = {0.f, 0.f}, a5 = {0.f, 0.f}, a6 = {0.f, 0.f}, a7 = {0.f, 0.f};
    #pragma unroll
    for (int l = 0; l < 64; l += 8) {
        const float2 v0 = __half22float2(g_scratch2[s_base[w][l + 0] + lane]);
        const float2 v1 = __half22float2(g_scratch2[s_base[w][l + 1] + lane]);
        const float2 v2 = __half22float2(g_scratch2[s_base[w][l + 2] + lane]);
        const float2 v3 = __half22float2(g_scratch2[s_base[w][l + 3] + lane]);
        const float2 v4 = __half22float2(g_scratch2[s_base[w][l + 4] + lane]);
        const float2 v5 = __half22float2(g_scratch2[s_base[w][l + 5] + lane]);
        const float2 v6 = __half22float2(g_scratch2[s_base[w][l + 6] + lane]);
        const float2 v7 = __half22float2(g_scratch2[s_base[w][l + 7] + lane]);
        a0.x += v0.x; a0.y += v0.y;  a1.x += v1.x; a1.y += v1.y;
        a2.x += v2.x; a2.y += v2.y;  a3.x += v3.x; a3.y += v3.y;
        a4.x += v4.x; a4.y += v4.y;  a5.x += v5.x; a5.y += v5.y;
        a6.x += v6.x; a6.y += v6.y;  a7.x += v7.x; a7.y += v7.y;
    }
    const float sx = ((a0.x + a1.x) + (a2.x + a3.x)) + ((a4.x + a5.x) + (a6.x + a7.x));
    const float sy = ((a0.y + a1.y) + (a2.y + a3.y)) + ((a4.y + a5.y) + (a6.y + a7.y));

    float p = exp2f(sx) + exp2f(sy);
    #pragma unroll
    for (int o = 16; o > 0; o >>= 1)
        p += __shfl_xor_sync(0xffffffffu, p, o);
    if (lane == 0) out[b] = p;
}

// ---------------------------------------------------------------------------
extern "C" void kernel_launch(void* const* d_in, const int* in_sizes, int n_in,
                              void* d_out, int out_size) {
    const float* eps = (const float*)d_in[1];
    float*       out = (float*)d_out;

    mark_partial <<<NGROUP, 256>>>(d_in[0]);
    reduce_rng   <<<64, 256>>>();
    eps_transpose<<<dim3(64, 32, 4), dim3(32, 8)>>>(eps);
    seggps_compute<<<8192 / 8, 256>>>(d_in[0], out);
}